// round 2
// baseline (speedup 1.0000x reference)
#include <cuda_runtime.h>

#define B    64
#define Nn   1024
#define IND  64
#define E    8
#define OUT  32
#define EO   (E*OUT)   // 256

// Scratch (allocation-free: __device__ globals)
__device__ float g_uhat[(size_t)B * E * Nn * OUT];  // [b][e][n][o]  67 MB
__device__ float g_blog[(size_t)B * Nn * E];        // [b][n][e]      2 MB
__device__ float g_v[B * E * OUT];                  // per-iter v    64 KB

// ---------------------------------------------------------------------------
// K1: per-n GEMM.  u_hat[b, e, n, o] = sum_i W[n,e,o,i] * u[b,n,i]
// One block per n. M=64 (b), N=256 (eo), K=64 (i). 8x8 register tiles.
// ---------------------------------------------------------------------------
__global__ __launch_bounds__(256, 2) void gemm_kernel(
    const float* __restrict__ u, const float* __restrict__ W)
{
    extern __shared__ float smem[];
    float* sW = smem;            // [IND][EO]  64*256 floats (k-major)
    float* sU = smem + IND * EO; // [IND][B]   64*64 floats (k-major)

    const int n   = blockIdx.x;
    const int tid = threadIdx.x;

    // --- Load W[n][eo][i] -> sW[i][eo] (one eo per thread; smem writes
    //     are lane-consecutive -> conflict free) ---
    {
        const float* Wn = W + (size_t)n * EO * IND + (size_t)tid * IND;
        #pragma unroll
        for (int i4 = 0; i4 < IND; i4 += 4) {
            float4 w = *reinterpret_cast<const float4*>(Wn + i4);
            sW[(i4 + 0) * EO + tid] = w.x;
            sW[(i4 + 1) * EO + tid] = w.y;
            sW[(i4 + 2) * EO + tid] = w.z;
            sW[(i4 + 3) * EO + tid] = w.w;
        }
    }
    // --- Load u[b][n][i] -> sU[i][b] ---
    {
        const int b  = tid & 63;
        const int iq = tid >> 6;            // 0..3 (16 i's each)
        const float* ub = u + ((size_t)b * Nn + n) * IND + iq * 16;
        #pragma unroll
        for (int j = 0; j < 16; j += 4) {
            float4 v = *reinterpret_cast<const float4*>(ub + j);
            const int i = iq * 16 + j;
            sU[(i + 0) * B + b] = v.x;
            sU[(i + 1) * B + b] = v.y;
            sU[(i + 2) * B + b] = v.z;
            sU[(i + 3) * B + b] = v.w;
        }
    }
    __syncthreads();

    const int b0  = (tid >> 5) * 8;   // 8 b-rows per thread
    const int eo0 = (tid & 31) * 8;   // 8 eo-cols per thread (within one e)

    float acc[8][8];
    #pragma unroll
    for (int ii = 0; ii < 8; ii++)
        #pragma unroll
        for (int jj = 0; jj < 8; jj++) acc[ii][jj] = 0.f;

    #pragma unroll 4
    for (int k = 0; k < IND; k++) {
        const float* su = sU + k * B  + b0;
        const float* sw = sW + k * EO + eo0;
        float uu[8], ww[8];
        float4 t;
        t = *reinterpret_cast<const float4*>(su);     uu[0]=t.x; uu[1]=t.y; uu[2]=t.z; uu[3]=t.w;
        t = *reinterpret_cast<const float4*>(su + 4); uu[4]=t.x; uu[5]=t.y; uu[6]=t.z; uu[7]=t.w;
        t = *reinterpret_cast<const float4*>(sw);     ww[0]=t.x; ww[1]=t.y; ww[2]=t.z; ww[3]=t.w;
        t = *reinterpret_cast<const float4*>(sw + 4); ww[4]=t.x; ww[5]=t.y; ww[6]=t.z; ww[7]=t.w;
        #pragma unroll
        for (int ii = 0; ii < 8; ii++)
            #pragma unroll
            for (int jj = 0; jj < 8; jj++)
                acc[ii][jj] = fmaf(uu[ii], ww[jj], acc[ii][jj]);
    }

    // --- Store: each thread owns 8 b x (one e, 8 consecutive o) ---
    const int e  = eo0 >> 5;
    const int o0 = eo0 & 31;
    #pragma unroll
    for (int ii = 0; ii < 8; ii++) {
        const int b = b0 + ii;
        float* dst = g_uhat + (((size_t)(b * E + e) * Nn + n) * OUT) + o0;
        *reinterpret_cast<float4*>(dst)     = make_float4(acc[ii][0], acc[ii][1], acc[ii][2], acc[ii][3]);
        *reinterpret_cast<float4*>(dst + 4) = make_float4(acc[ii][4], acc[ii][5], acc[ii][6], acc[ii][7]);
    }
}

// ---------------------------------------------------------------------------
// Block-level helper: reduce 256-thread partials (layout [g=8][o=32]) to 32
// values, squash, write v (and optionally d_out).
// ---------------------------------------------------------------------------
__device__ __forceinline__ void reduce_squash_store(
    float acc, int tid, int be, float* red, float* out_final)
{
    red[tid] = acc;
    __syncthreads();
    if (tid < 128) red[tid] += red[tid + 128];
    __syncthreads();
    if (tid < 64)  red[tid] += red[tid + 64];
    __syncthreads();
    if (tid < 32) {
        float s  = red[tid] + red[tid + 32];
        float sq = s * s;
        #pragma unroll
        for (int off = 16; off > 0; off >>= 1)
            sq += __shfl_xor_sync(0xFFFFFFFFu, sq, off);
        const float norm  = sqrtf(sq);
        const float scale = sq / (1.f + sq) / (norm + 1e-8f);
        const float v = s * scale;
        if (out_final) out_final[be * OUT + tid] = v;
        else           g_v[be * OUT + tid] = v;
    }
}

// ---------------------------------------------------------------------------
// K2: iteration 0 — c is uniform 1/8. s = (1/8) sum_n u_hat; v0 = squash(s)
// ---------------------------------------------------------------------------
__global__ __launch_bounds__(256) void reduce0_kernel()
{
    const int be  = blockIdx.x;                  // b*8 + e
    const int tid = threadIdx.x;
    const float* ptr = g_uhat + (size_t)be * Nn * OUT;
    const int o = tid & 31, g = tid >> 5;
    float acc = 0.f;
    #pragma unroll 8
    for (int n = g; n < Nn; n += 8) acc += ptr[n * OUT + o];
    __shared__ float red[256];
    reduce_squash_store(acc * 0.125f, tid, be, red, nullptr);
}

// ---------------------------------------------------------------------------
// K3/K5: agreement — blog[b,n,e] (+)= dot_o(u_hat[b,e,n,:], v[b,e,:])
// ---------------------------------------------------------------------------
__global__ __launch_bounds__(256) void agree_kernel(int first)
{
    const int be = blockIdx.x;
    const int b = be >> 3, e = be & 7;
    const int tid = threadIdx.x;
    const float* ptr = g_uhat + (size_t)be * Nn * OUT;

    __shared__ float vs[OUT];
    if (tid < OUT) vs[tid] = g_v[be * OUT + tid];
    __syncthreads();

    for (int n = tid; n < Nn; n += 256) {
        const float4* row = reinterpret_cast<const float4*>(ptr + n * OUT);
        float uv = 0.f;
        #pragma unroll
        for (int j = 0; j < 8; j++) {
            float4 x = row[j];
            uv += x.x * vs[j*4+0] + x.y * vs[j*4+1]
                + x.z * vs[j*4+2] + x.w * vs[j*4+3];
        }
        float* bp = g_blog + ((size_t)b * Nn + n) * E + e;
        if (first) *bp = uv; else *bp += uv;
    }
}

// ---------------------------------------------------------------------------
// K4/K6: softmax over E, weighted reduce over n, squash.
// ---------------------------------------------------------------------------
__global__ __launch_bounds__(256) void route_kernel(float* __restrict__ out, int final_iter)
{
    const int be = blockIdx.x;
    const int b = be >> 3, e = be & 7;
    const int tid = threadIdx.x;

    __shared__ float c[Nn];        // softmax coeff for this (b,e)
    __shared__ float red[256];

    // Phase 1: compute c[n] = softmax_e(blog[b,n,:])[e]
    for (int n = tid; n < Nn; n += 256) {
        const float* bl = g_blog + ((size_t)b * Nn + n) * E;
        float4 x0 = *reinterpret_cast<const float4*>(bl);
        float4 x1 = *reinterpret_cast<const float4*>(bl + 4);
        float xs[8] = {x0.x, x0.y, x0.z, x0.w, x1.x, x1.y, x1.z, x1.w};
        float m = xs[0];
        #pragma unroll
        for (int j = 1; j < 8; j++) m = fmaxf(m, xs[j]);
        float d = 0.f;
        #pragma unroll
        for (int j = 0; j < 8; j++) d += expf(xs[j] - m);
        c[n] = expf(xs[e] - m) / d;
    }
    __syncthreads();

    // Phase 2: s[o] = sum_n c[n] * u_hat[b,e,n,o]
    const float* ptr = g_uhat + (size_t)be * Nn * OUT;
    const int o = tid & 31, g = tid >> 5;
    float acc = 0.f;
    #pragma unroll 8
    for (int n = g; n < Nn; n += 8) acc = fmaf(c[n], ptr[n * OUT + o], acc);

    reduce_squash_store(acc, tid, be, red, final_iter ? out : nullptr);
}

// ---------------------------------------------------------------------------
extern "C" void kernel_launch(void* const* d_in, const int* in_sizes, int n_in,
                              void* d_out, int out_size)
{
    const float* u = (const float*)d_in[0];   // [B, N, IND]
    const float* W = (const float*)d_in[1];   // [N, E, OUT, IND]
    float* out = (float*)d_out;               // [B, E, OUT]

    const int gemm_smem = (IND * EO + IND * B) * (int)sizeof(float); // 80 KB
    cudaFuncSetAttribute(gemm_kernel, cudaFuncAttributeMaxDynamicSharedMemorySize, gemm_smem);

    gemm_kernel<<<Nn, 256, gemm_smem>>>(u, W);
    reduce0_kernel<<<B * E, 256>>>();          // v0
    agree_kernel<<<B * E, 256>>>(1);           // blog = uv(v0)
    route_kernel<<<B * E, 256>>>(out, 0);      // v1
    agree_kernel<<<B * E, 256>>>(0);           // blog += uv(v1)
    route_kernel<<<B * E, 256>>>(out, 1);      // v2 -> d_out
}

// round 8
// speedup vs baseline: 1.3101x; 1.3101x over previous
#include <cuda_runtime.h>
#include <cuda_bf16.h>
#include <cstdint>

#define B    64
#define Nn   1024
#define IND  64
#define E    8
#define OUT  32
#define EO   (E*OUT)   // 256
#define KP   (IND/2)   // 32 bf16-pairs along k

// Scratch (allocation-free: __device__ globals)
__device__ float g_uhat[(size_t)B * E * Nn * OUT];  // [b][e][n][o]  67 MB
__device__ float g_blog[(size_t)B * Nn * E];        // [b][n][e]      2 MB
__device__ float g_v[B * E * OUT];                  // per-iter v    64 KB

// ---------------------------------------------------------------------------
// helpers
// ---------------------------------------------------------------------------
__device__ __forceinline__ uint32_t pack_bf16(float x, float y) {
    __nv_bfloat162 h = __floats2bfloat162_rn(x, y);  // .x (low) = x
    return *reinterpret_cast<uint32_t*>(&h);
}

__device__ __forceinline__ void mma_bf16(float (&c)[4], const uint32_t a[4],
                                         const uint32_t b[2]) {
    asm volatile(
        "mma.sync.aligned.m16n8k16.row.col.f32.bf16.bf16.f32 "
        "{%0,%1,%2,%3}, {%4,%5,%6,%7}, {%8,%9}, {%0,%1,%2,%3};"
        : "+f"(c[0]), "+f"(c[1]), "+f"(c[2]), "+f"(c[3])
        : "r"(a[0]), "r"(a[1]), "r"(a[2]), "r"(a[3]), "r"(b[0]), "r"(b[1]));
}

// ---------------------------------------------------------------------------
// K1: per-n GEMM via split-bf16 HMMA.
//   u_hat[b, e, n, o] = sum_i W[n,e,o,i] * u[b,n,i]
// One block per n. 256 threads = 8 warps; warp w owns e = w (all 64 b,
// 32 o) as 4 m16-tiles x 4 n8-tiles. Split fp32 = hi + lo (bf16):
// acc += Ah*Bh + Ah*Bl + Al*Bh  (Al*Bl ~1e-6, dropped).
// ---------------------------------------------------------------------------
#define APAD 33
#define WPAD 260

__global__ __launch_bounds__(256, 1) void gemm_kernel(
    const float* __restrict__ u, const float* __restrict__ W)
{
    extern __shared__ uint32_t smem[];
    uint32_t* aHi = smem;                 // [64][APAD]
    uint32_t* aLo = aHi + 64 * APAD;
    uint32_t* wHi = aLo + 64 * APAD;      // [KP][WPAD]
    uint32_t* wLo = wHi + KP * WPAD;

    const int n   = blockIdx.x;
    const int tid = threadIdx.x;

    // --- convert W[n][eo][0..63] -> wHi/wLo[kp][eo], one eo per thread ---
    {
        const float* Wn = W + (size_t)n * EO * IND + (size_t)tid * IND;
        #pragma unroll
        for (int p = 0; p < KP; p += 2) {
            float4 x = *reinterpret_cast<const float4*>(Wn + 2 * p);
            float h0 = __bfloat162float(__float2bfloat16(x.x));
            float h1 = __bfloat162float(__float2bfloat16(x.y));
            float h2 = __bfloat162float(__float2bfloat16(x.z));
            float h3 = __bfloat162float(__float2bfloat16(x.w));
            wHi[p * WPAD + tid]       = pack_bf16(h0, h1);
            wHi[(p + 1) * WPAD + tid] = pack_bf16(h2, h3);
            wLo[p * WPAD + tid]       = pack_bf16(x.x - h0, x.y - h1);
            wLo[(p + 1) * WPAD + tid] = pack_bf16(x.z - h2, x.w - h3);
        }
    }
    // --- convert u[b][n][0..63] -> aHi/aLo[b][kp] ---
    {
        const int b  = tid & 63;
        const int iq = tid >> 6;   // 0..3, 16 i's each
        const float* ub = u + ((size_t)b * Nn + n) * IND + iq * 16;
        #pragma unroll
        for (int j = 0; j < 16; j += 4) {
            float4 x = *reinterpret_cast<const float4*>(ub + j);
            const int p = (iq * 16 + j) >> 1;
            float h0 = __bfloat162float(__float2bfloat16(x.x));
            float h1 = __bfloat162float(__float2bfloat16(x.y));
            float h2 = __bfloat162float(__float2bfloat16(x.z));
            float h3 = __bfloat162float(__float2bfloat16(x.w));
            aHi[b * APAD + p]     = pack_bf16(h0, h1);
            aHi[b * APAD + p + 1] = pack_bf16(h2, h3);
            aLo[b * APAD + p]     = pack_bf16(x.x - h0, x.y - h1);
            aLo[b * APAD + p + 1] = pack_bf16(x.z - h2, x.w - h3);
        }
    }
    __syncthreads();

    const int w   = tid >> 5;          // warp = e
    const int l   = tid & 31;
    const int g   = l >> 2;            // groupID
    const int tig = l & 3;             // thread-in-group

    float acc[4][4][4];
    #pragma unroll
    for (int m = 0; m < 4; m++)
        #pragma unroll
        for (int t = 0; t < 4; t++)
            #pragma unroll
            for (int r = 0; r < 4; r++) acc[m][t][r] = 0.f;

    #pragma unroll
    for (int ks = 0; ks < 4; ks++) {
        const int kp0 = ks * 8 + tig;
        uint32_t ah[4][4], al[4][4], bh[4][2], bl[4][2];
        #pragma unroll
        for (int m = 0; m < 4; m++) {
            const int r0 = m * 16 + g;
            ah[m][0] = aHi[r0 * APAD + kp0];
            ah[m][1] = aHi[(r0 + 8) * APAD + kp0];
            ah[m][2] = aHi[r0 * APAD + kp0 + 4];
            ah[m][3] = aHi[(r0 + 8) * APAD + kp0 + 4];
            al[m][0] = aLo[r0 * APAD + kp0];
            al[m][1] = aLo[(r0 + 8) * APAD + kp0];
            al[m][2] = aLo[r0 * APAD + kp0 + 4];
            al[m][3] = aLo[(r0 + 8) * APAD + kp0 + 4];
        }
        #pragma unroll
        for (int t = 0; t < 4; t++) {
            const int eo = w * 32 + t * 8 + g;
            bh[t][0] = wHi[kp0 * WPAD + eo];
            bh[t][1] = wHi[(kp0 + 4) * WPAD + eo];
            bl[t][0] = wLo[kp0 * WPAD + eo];
            bl[t][1] = wLo[(kp0 + 4) * WPAD + eo];
        }
        #pragma unroll
        for (int m = 0; m < 4; m++)
            #pragma unroll
            for (int t = 0; t < 4; t++) {
                mma_bf16(acc[m][t], ah[m], bh[t]);
                mma_bf16(acc[m][t], ah[m], bl[t]);
                mma_bf16(acc[m][t], al[m], bh[t]);
            }
    }

    // --- store: c0,c1 -> row (m*16+g), o=2*tig+t*8; c2,c3 -> row +8 ---
    #pragma unroll
    for (int m = 0; m < 4; m++) {
        const int b0 = m * 16 + g;
        #pragma unroll
        for (int t = 0; t < 4; t++) {
            const int o = t * 8 + 2 * tig;
            float* d0 = g_uhat + (((size_t)(b0 * E + w) * Nn + n) * OUT) + o;
            float* d1 = g_uhat + (((size_t)((b0 + 8) * E + w) * Nn + n) * OUT) + o;
            *reinterpret_cast<float2*>(d0) = make_float2(acc[m][t][0], acc[m][t][1]);
            *reinterpret_cast<float2*>(d1) = make_float2(acc[m][t][2], acc[m][t][3]);
        }
    }
}

// ---------------------------------------------------------------------------
// Routing: one block per b, 1024 threads = 32 warps.
// Lane mapping: e = (lane>>2), o8 = (lane&3)*8 (8 o's per lane).
// Warp w handles n = w, w+32, ...
// ---------------------------------------------------------------------------
#define RPAD 264   // row stride (floats) for the block-reduce scratch

__device__ __forceinline__ void block_reduce_squash(
    float acc[8], float* red, int tid, int b, float pre_scale, float* out)
{
    const int w = tid >> 5, l = tid & 31;
    // sequential 32B/lane stores -> conflict-free
    *reinterpret_cast<float4*>(red + w * RPAD + l * 8)     = make_float4(acc[0], acc[1], acc[2], acc[3]);
    *reinterpret_cast<float4*>(red + w * RPAD + l * 8 + 4) = make_float4(acc[4], acc[5], acc[6], acc[7]);
    __syncthreads();
    if (tid < 256) {
        float s = 0.f;
        #pragma unroll
        for (int ww = 0; ww < 32; ww++) s += red[ww * RPAD + tid];
        s *= pre_scale;
        // warp (tid>>5) == e; 32 lanes == o
        float sq = s * s;
        #pragma unroll
        for (int off = 16; off > 0; off >>= 1)
            sq += __shfl_xor_sync(0xFFFFFFFFu, sq, off);
        const float norm  = sqrtf(sq);
        const float scale = sq / (1.f + sq) / (norm + 1e-8f);
        // IMPORTANT: g_v referenced from DEVICE code (host-side symbol address
        // is invalid as a kernel arg — that was the R3 bug).
        float* dst = (out != nullptr) ? out : g_v;
        dst[b * EO + tid] = s * scale;
    }
}

// pass A: v0 = squash(mean_n u_hat)
__global__ __launch_bounds__(1024, 1) void routeA_kernel()
{
    __shared__ float red[32 * RPAD];
    const int b = blockIdx.x, tid = threadIdx.x;
    const int w = tid >> 5, l = tid & 31;
    const int e = l >> 2, o8 = (l & 3) * 8;
    const float* base = g_uhat + ((size_t)(b * E + e) * Nn) * OUT + o8;

    float acc[8];
    #pragma unroll
    for (int j = 0; j < 8; j++) acc[j] = 0.f;

    for (int n = w; n < Nn; n += 32) {
        float4 p0 = *reinterpret_cast<const float4*>(base + (size_t)n * OUT);
        float4 p1 = *reinterpret_cast<const float4*>(base + (size_t)n * OUT + 4);
        acc[0] += p0.x; acc[1] += p0.y; acc[2] += p0.z; acc[3] += p0.w;
        acc[4] += p1.x; acc[5] += p1.y; acc[6] += p1.z; acc[7] += p1.w;
    }
    block_reduce_squash(acc, red, tid, b, 0.125f, nullptr);
}

// passes B/C: fused agreement + softmax + weighted reduce + squash
__global__ __launch_bounds__(1024, 1) void routeBC_kernel(float* __restrict__ out, int first)
{
    __shared__ float red[32 * RPAD];
    const int b = blockIdx.x, tid = threadIdx.x;
    const int w = tid >> 5, l = tid & 31;
    const int e = l >> 2, o8 = (l & 3) * 8;
    const float* base = g_uhat + ((size_t)(b * E + e) * Nn) * OUT + o8;

    float v8[8];
    {
        const float* vp = g_v + (b * E + e) * OUT + o8;
        float4 q0 = *reinterpret_cast<const float4*>(vp);
        float4 q1 = *reinterpret_cast<const float4*>(vp + 4);
        v8[0]=q0.x; v8[1]=q0.y; v8[2]=q0.z; v8[3]=q0.w;
        v8[4]=q1.x; v8[5]=q1.y; v8[6]=q1.z; v8[7]=q1.w;
    }

    float acc[8];
    #pragma unroll
    for (int j = 0; j < 8; j++) acc[j] = 0.f;

    for (int n = w; n < Nn; n += 32) {
        float x[8];
        float4 p0 = *reinterpret_cast<const float4*>(base + (size_t)n * OUT);
        float4 p1 = *reinterpret_cast<const float4*>(base + (size_t)n * OUT + 4);
        x[0]=p0.x; x[1]=p0.y; x[2]=p0.z; x[3]=p0.w;
        x[4]=p1.x; x[5]=p1.y; x[6]=p1.z; x[7]=p1.w;

        // uv_e = dot over o (4-lane group reduce)
        float uv = 0.f;
        #pragma unroll
        for (int j = 0; j < 8; j++) uv = fmaf(x[j], v8[j], uv);
        uv += __shfl_xor_sync(0xFFFFFFFFu, uv, 1);
        uv += __shfl_xor_sync(0xFFFFFFFFu, uv, 2);

        float logit = uv;
        if (first) {
            // blog = uv(v0); gather uv of group (l&7), lanes 0..7 store
            float bl = __shfl_sync(0xFFFFFFFFu, uv, (l & 7) * 4);
            if (l < 8) g_blog[((size_t)b * Nn + n) * E + l] = bl;
        } else {
            logit += g_blog[((size_t)b * Nn + n) * E + e];
        }

        // softmax over e (values identical within each 4-lane group)
        float m = logit;
        m = fmaxf(m, __shfl_xor_sync(0xFFFFFFFFu, m, 4));
        m = fmaxf(m, __shfl_xor_sync(0xFFFFFFFFu, m, 8));
        m = fmaxf(m, __shfl_xor_sync(0xFFFFFFFFu, m, 16));
        float ex = __expf(logit - m);
        float den = ex;
        den += __shfl_xor_sync(0xFFFFFFFFu, den, 4);
        den += __shfl_xor_sync(0xFFFFFFFFu, den, 8);
        den += __shfl_xor_sync(0xFFFFFFFFu, den, 16);
        const float c = __fdividef(ex, den);

        #pragma unroll
        for (int j = 0; j < 8; j++) acc[j] = fmaf(c, x[j], acc[j]);
    }
    block_reduce_squash(acc, red, tid, b, 1.0f, out);
}

// ---------------------------------------------------------------------------
extern "C" void kernel_launch(void* const* d_in, const int* in_sizes, int n_in,
                              void* d_out, int out_size)
{
    const float* u = (const float*)d_in[0];   // [B, N, IND]
    const float* W = (const float*)d_in[1];   // [N, E, OUT, IND]
    float* out = (float*)d_out;               // [B, E, OUT]

    const int gemm_smem = (2 * 64 * APAD + 2 * KP * WPAD) * (int)sizeof(uint32_t);
    cudaFuncSetAttribute(gemm_kernel, cudaFuncAttributeMaxDynamicSharedMemorySize, gemm_smem);

    gemm_kernel<<<Nn, 256, gemm_smem>>>(u, W);
    routeA_kernel<<<B, 1024>>>();                 // v0
    routeBC_kernel<<<B, 1024>>>(nullptr, 1);      // blog = uv(v0); v1 -> g_v
    routeBC_kernel<<<B, 1024>>>(out, 0);          // logits = blog + uv(v1); v2 -> out
}

// round 9
// speedup vs baseline: 1.4176x; 1.0821x over previous
#include <cuda_runtime.h>
#include <cuda_bf16.h>
#include <cstdint>

#define B    64
#define Nn   1024
#define IND  64
#define E    8
#define OUT  32
#define EO   (E*OUT)   // 256
#define KP   (IND/2)   // 32 bf16-pairs along k

#define SPLIT   8
#define NCHUNK  (Nn / SPLIT)      // 128 n's per routing block
#define RT      512               // routing threads per block (16 warps)
#define RW      (RT / 32)         // 16 warps

// Scratch (allocation-free: __device__ globals)
__device__ float g_uhat[(size_t)B * E * Nn * OUT];  // [b][e][n][o]  67 MB
__device__ float g_blog[(size_t)B * Nn * E];        // [b][n][e]      2 MB
__device__ float g_v[B * E * OUT];                  // per-iter v    64 KB
__device__ float g_part[(size_t)B * SPLIT * EO];    // partial s    512 KB

// ---------------------------------------------------------------------------
// helpers
// ---------------------------------------------------------------------------
__device__ __forceinline__ uint32_t pack_bf16(float x, float y) {
    __nv_bfloat162 h = __floats2bfloat162_rn(x, y);  // .x (low) = x
    return *reinterpret_cast<uint32_t*>(&h);
}

__device__ __forceinline__ void mma_bf16(float (&c)[4], const uint32_t a[4],
                                         const uint32_t b[2]) {
    asm volatile(
        "mma.sync.aligned.m16n8k16.row.col.f32.bf16.bf16.f32 "
        "{%0,%1,%2,%3}, {%4,%5,%6,%7}, {%8,%9}, {%0,%1,%2,%3};"
        : "+f"(c[0]), "+f"(c[1]), "+f"(c[2]), "+f"(c[3])
        : "r"(a[0]), "r"(a[1]), "r"(a[2]), "r"(a[3]), "r"(b[0]), "r"(b[1]));
}

// ---------------------------------------------------------------------------
// K1: per-n GEMM via split-bf16 HMMA (unchanged from R8 — near memory cap).
// ---------------------------------------------------------------------------
#define APAD 33
#define WPAD 260

__global__ __launch_bounds__(256, 1) void gemm_kernel(
    const float* __restrict__ u, const float* __restrict__ W)
{
    extern __shared__ uint32_t smem[];
    uint32_t* aHi = smem;                 // [64][APAD]
    uint32_t* aLo = aHi + 64 * APAD;
    uint32_t* wHi = aLo + 64 * APAD;      // [KP][WPAD]
    uint32_t* wLo = wHi + KP * WPAD;

    const int n   = blockIdx.x;
    const int tid = threadIdx.x;

    {
        const float* Wn = W + (size_t)n * EO * IND + (size_t)tid * IND;
        #pragma unroll
        for (int p = 0; p < KP; p += 2) {
            float4 x = *reinterpret_cast<const float4*>(Wn + 2 * p);
            float h0 = __bfloat162float(__float2bfloat16(x.x));
            float h1 = __bfloat162float(__float2bfloat16(x.y));
            float h2 = __bfloat162float(__float2bfloat16(x.z));
            float h3 = __bfloat162float(__float2bfloat16(x.w));
            wHi[p * WPAD + tid]       = pack_bf16(h0, h1);
            wHi[(p + 1) * WPAD + tid] = pack_bf16(h2, h3);
            wLo[p * WPAD + tid]       = pack_bf16(x.x - h0, x.y - h1);
            wLo[(p + 1) * WPAD + tid] = pack_bf16(x.z - h2, x.w - h3);
        }
    }
    {
        const int b  = tid & 63;
        const int iq = tid >> 6;
        const float* ub = u + ((size_t)b * Nn + n) * IND + iq * 16;
        #pragma unroll
        for (int j = 0; j < 16; j += 4) {
            float4 x = *reinterpret_cast<const float4*>(ub + j);
            const int p = (iq * 16 + j) >> 1;
            float h0 = __bfloat162float(__float2bfloat16(x.x));
            float h1 = __bfloat162float(__float2bfloat16(x.y));
            float h2 = __bfloat162float(__float2bfloat16(x.z));
            float h3 = __bfloat162float(__float2bfloat16(x.w));
            aHi[b * APAD + p]     = pack_bf16(h0, h1);
            aHi[b * APAD + p + 1] = pack_bf16(h2, h3);
            aLo[b * APAD + p]     = pack_bf16(x.x - h0, x.y - h1);
            aLo[b * APAD + p + 1] = pack_bf16(x.z - h2, x.w - h3);
        }
    }
    __syncthreads();

    const int w   = tid >> 5;
    const int l   = tid & 31;
    const int g   = l >> 2;
    const int tig = l & 3;

    float acc[4][4][4];
    #pragma unroll
    for (int m = 0; m < 4; m++)
        #pragma unroll
        for (int t = 0; t < 4; t++)
            #pragma unroll
            for (int r = 0; r < 4; r++) acc[m][t][r] = 0.f;

    #pragma unroll
    for (int ks = 0; ks < 4; ks++) {
        const int kp0 = ks * 8 + tig;
        uint32_t ah[4][4], al[4][4], bh[4][2], bl[4][2];
        #pragma unroll
        for (int m = 0; m < 4; m++) {
            const int r0 = m * 16 + g;
            ah[m][0] = aHi[r0 * APAD + kp0];
            ah[m][1] = aHi[(r0 + 8) * APAD + kp0];
            ah[m][2] = aHi[r0 * APAD + kp0 + 4];
            ah[m][3] = aHi[(r0 + 8) * APAD + kp0 + 4];
            al[m][0] = aLo[r0 * APAD + kp0];
            al[m][1] = aLo[(r0 + 8) * APAD + kp0];
            al[m][2] = aLo[r0 * APAD + kp0 + 4];
            al[m][3] = aLo[(r0 + 8) * APAD + kp0 + 4];
        }
        #pragma unroll
        for (int t = 0; t < 4; t++) {
            const int eo = w * 32 + t * 8 + g;
            bh[t][0] = wHi[kp0 * WPAD + eo];
            bh[t][1] = wHi[(kp0 + 4) * WPAD + eo];
            bl[t][0] = wLo[kp0 * WPAD + eo];
            bl[t][1] = wLo[(kp0 + 4) * WPAD + eo];
        }
        #pragma unroll
        for (int m = 0; m < 4; m++)
            #pragma unroll
            for (int t = 0; t < 4; t++) {
                mma_bf16(acc[m][t], ah[m], bh[t]);
                mma_bf16(acc[m][t], ah[m], bl[t]);
                mma_bf16(acc[m][t], al[m], bh[t]);
            }
    }

    #pragma unroll
    for (int m = 0; m < 4; m++) {
        const int b0 = m * 16 + g;
        #pragma unroll
        for (int t = 0; t < 4; t++) {
            const int o = t * 8 + 2 * tig;
            float* d0 = g_uhat + (((size_t)(b0 * E + w) * Nn + n) * OUT) + o;
            float* d1 = g_uhat + (((size_t)((b0 + 8) * E + w) * Nn + n) * OUT) + o;
            *reinterpret_cast<float2*>(d0) = make_float2(acc[m][t][0], acc[m][t][1]);
            *reinterpret_cast<float2*>(d1) = make_float2(acc[m][t][2], acc[m][t][3]);
        }
    }
}

// ---------------------------------------------------------------------------
// Routing, two-stage. Part kernels: grid = B*SPLIT blocks x 512 threads.
// Block (b, sp) covers n in [sp*NCHUNK, (sp+1)*NCHUNK).
// Lane mapping: e = (lane>>2), o8 = (lane&3)*8.
// ---------------------------------------------------------------------------
#define RPAD 264

__device__ __forceinline__ void block_partial_store(
    float acc[8], float* red, int tid, int blk)
{
    const int w = tid >> 5, l = tid & 31;
    *reinterpret_cast<float4*>(red + w * RPAD + l * 8)     = make_float4(acc[0], acc[1], acc[2], acc[3]);
    *reinterpret_cast<float4*>(red + w * RPAD + l * 8 + 4) = make_float4(acc[4], acc[5], acc[6], acc[7]);
    __syncthreads();
    if (tid < EO) {
        float s = 0.f;
        #pragma unroll
        for (int ww = 0; ww < RW; ww++) s += red[ww * RPAD + tid];
        g_part[(size_t)blk * EO + tid] = s;
    }
}

// pass A partial: sum_n u_hat over this block's n-chunk
__global__ __launch_bounds__(RT, 2) void routeA_part()
{
    __shared__ float red[RW * RPAD];
    const int blk = blockIdx.x;
    const int b = blk / SPLIT, sp = blk % SPLIT;
    const int tid = threadIdx.x;
    const int w = tid >> 5, l = tid & 31;
    const int e = l >> 2, o8 = (l & 3) * 8;
    const float* base = g_uhat + ((size_t)(b * E + e) * Nn) * OUT + o8;
    const int n0 = sp * NCHUNK;

    float acc[8];
    #pragma unroll
    for (int j = 0; j < 8; j++) acc[j] = 0.f;

    #pragma unroll 2
    for (int n = n0 + w; n < n0 + NCHUNK; n += RW) {
        float4 p0 = *reinterpret_cast<const float4*>(base + (size_t)n * OUT);
        float4 p1 = *reinterpret_cast<const float4*>(base + (size_t)n * OUT + 4);
        acc[0] += p0.x; acc[1] += p0.y; acc[2] += p0.z; acc[3] += p0.w;
        acc[4] += p1.x; acc[5] += p1.y; acc[6] += p1.z; acc[7] += p1.w;
    }
    block_partial_store(acc, red, tid, blk);
}

// passes B/C partial: agreement + softmax + weighted partial sum
__global__ __launch_bounds__(RT, 2) void routeBC_part(int first)
{
    __shared__ float red[RW * RPAD];
    const int blk = blockIdx.x;
    const int b = blk / SPLIT, sp = blk % SPLIT;
    const int tid = threadIdx.x;
    const int w = tid >> 5, l = tid & 31;
    const int e = l >> 2, o8 = (l & 3) * 8;
    const float* base = g_uhat + ((size_t)(b * E + e) * Nn) * OUT + o8;
    const int n0 = sp * NCHUNK;

    float v8[8];
    {
        const float* vp = g_v + (b * E + e) * OUT + o8;
        float4 q0 = *reinterpret_cast<const float4*>(vp);
        float4 q1 = *reinterpret_cast<const float4*>(vp + 4);
        v8[0]=q0.x; v8[1]=q0.y; v8[2]=q0.z; v8[3]=q0.w;
        v8[4]=q1.x; v8[5]=q1.y; v8[6]=q1.z; v8[7]=q1.w;
    }

    float acc[8];
    #pragma unroll
    for (int j = 0; j < 8; j++) acc[j] = 0.f;

    for (int n = n0 + w; n < n0 + NCHUNK; n += RW) {
        float x[8];
        float4 p0 = *reinterpret_cast<const float4*>(base + (size_t)n * OUT);
        float4 p1 = *reinterpret_cast<const float4*>(base + (size_t)n * OUT + 4);
        x[0]=p0.x; x[1]=p0.y; x[2]=p0.z; x[3]=p0.w;
        x[4]=p1.x; x[5]=p1.y; x[6]=p1.z; x[7]=p1.w;

        // uv_e = dot over o (4-lane group reduce)
        float uv = 0.f;
        #pragma unroll
        for (int j = 0; j < 8; j++) uv = fmaf(x[j], v8[j], uv);
        uv += __shfl_xor_sync(0xFFFFFFFFu, uv, 1);
        uv += __shfl_xor_sync(0xFFFFFFFFu, uv, 2);

        float logit = uv;
        if (first) {
            float bl = __shfl_sync(0xFFFFFFFFu, uv, (l & 7) * 4);
            if (l < 8) g_blog[((size_t)b * Nn + n) * E + l] = bl;
        } else {
            logit += g_blog[((size_t)b * Nn + n) * E + e];
        }

        // softmax over e (identical within each 4-lane group)
        float m = logit;
        m = fmaxf(m, __shfl_xor_sync(0xFFFFFFFFu, m, 4));
        m = fmaxf(m, __shfl_xor_sync(0xFFFFFFFFu, m, 8));
        m = fmaxf(m, __shfl_xor_sync(0xFFFFFFFFu, m, 16));
        float ex = __expf(logit - m);
        float den = ex;
        den += __shfl_xor_sync(0xFFFFFFFFu, den, 4);
        den += __shfl_xor_sync(0xFFFFFFFFu, den, 8);
        den += __shfl_xor_sync(0xFFFFFFFFu, den, 16);
        const float c = __fdividef(ex, den);

        #pragma unroll
        for (int j = 0; j < 8; j++) acc[j] = fmaf(c, x[j], acc[j]);
    }
    block_partial_store(acc, red, tid, blk);
}

// finish: sum SPLIT partials, squash, write g_v (out==nullptr) or out.
__global__ __launch_bounds__(EO, 8) void finish_kernel(float* __restrict__ out, float pre_scale)
{
    const int b = blockIdx.x, tid = threadIdx.x;  // tid: e=tid>>5, o=tid&31
    float s = 0.f;
    #pragma unroll
    for (int k = 0; k < SPLIT; k++)
        s += g_part[((size_t)b * SPLIT + k) * EO + tid];
    s *= pre_scale;

    float sq = s * s;
    #pragma unroll
    for (int off = 16; off > 0; off >>= 1)
        sq += __shfl_xor_sync(0xFFFFFFFFu, sq, off);
    const float norm  = sqrtf(sq);
    const float scale = sq / (1.f + sq) / (norm + 1e-8f);
    float* dst = (out != nullptr) ? out : g_v;   // device-side symbol ref
    dst[b * EO + tid] = s * scale;
}

// ---------------------------------------------------------------------------
extern "C" void kernel_launch(void* const* d_in, const int* in_sizes, int n_in,
                              void* d_out, int out_size)
{
    const float* u = (const float*)d_in[0];   // [B, N, IND]
    const float* W = (const float*)d_in[1];   // [N, E, OUT, IND]
    float* out = (float*)d_out;               // [B, E, OUT]

    const int gemm_smem = (2 * 64 * APAD + 2 * KP * WPAD) * (int)sizeof(uint32_t);
    cudaFuncSetAttribute(gemm_kernel, cudaFuncAttributeMaxDynamicSharedMemorySize, gemm_smem);

    gemm_kernel<<<Nn, 256, gemm_smem>>>(u, W);

    routeA_part<<<B * SPLIT, RT>>>();
    finish_kernel<<<B, EO>>>(nullptr, 0.125f);       // v0 -> g_v

    routeBC_part<<<B * SPLIT, RT>>>(1);              // blog = uv(v0)
    finish_kernel<<<B, EO>>>(nullptr, 1.0f);         // v1 -> g_v

    routeBC_part<<<B * SPLIT, RT>>>(0);              // logits = blog + uv(v1)
    finish_kernel<<<B, EO>>>(out, 1.0f);             // v2 -> out
}